// round 1
// baseline (speedup 1.0000x reference)
#include <cuda_runtime.h>
#include <math.h>

#define E 256
#define KSEL 8
#define BETA 1000000.0f
#define FULL 0xFFFFFFFFu

// One warp per row. Each lane holds 8 contiguous floats (two float4 loads).
// 8 rounds of warp-argmax-with-exclusion find the top-8; a bitmask selects
// original value vs BETA on the way out.
__global__ __launch_bounds__(256) void keep_topk_kernel(
    const float* __restrict__ x, float* __restrict__ out, int n_rows)
{
    int warp = blockIdx.x * (blockDim.x >> 5) + (threadIdx.x >> 5);
    int lane = threadIdx.x & 31;
    if (warp >= n_rows) return;

    const float4* in4 = reinterpret_cast<const float4*>(x) + (size_t)warp * (E / 4);
    float4* out4 = reinterpret_cast<float4*>(out) + (size_t)warp * (E / 4);

    // Lane l owns elements [4l..4l+3] and [128+4l..128+4l+3] of the row.
    float4 A = in4[lane];
    float4 B = in4[lane + 32];

    float w[8] = {A.x, A.y, A.z, A.w, B.x, B.y, B.z, B.w};
    unsigned sel = 0;

    #pragma unroll
    for (int r = 0; r < KSEL; r++) {
        // Local argmax over remaining values; strict '>' with ascending j
        // keeps the lowest local slot, i.e. the lowest global index locally.
        float bv = w[0];
        int bi = 0;
        #pragma unroll
        for (int j = 1; j < 8; j++) {
            if (w[j] > bv) { bv = w[j]; bi = j; }
        }

        // Warp max (value only): 5 butterfly shuffles, all lanes converge.
        float wv = bv;
        #pragma unroll
        for (int off = 16; off; off >>= 1)
            wv = fmaxf(wv, __shfl_xor_sync(FULL, wv, off));

        unsigned cand = __ballot_sync(FULL, bv == wv);
        if (__popc(cand) > 1) {
            // Rare tie across lanes: pick the lowest GLOBAL index to match
            // jax.lax.top_k tie-breaking exactly. Warp-uniform branch.
            int gidx = ((bi >> 2) << 7) + lane * 4 + (bi & 3);
            int gi = (bv == wv) ? gidx : 0x7fffffff;
            #pragma unroll
            for (int off = 16; off; off >>= 1)
                gi = min(gi, __shfl_xor_sync(FULL, gi, off));
            if (bv == wv && ((bi >> 2) << 7) + lane * 4 + (bi & 3) == gi) {
                w[bi] = -INFINITY;
                sel |= 1u << bi;
            }
        } else {
            if (cand & (1u << lane)) {
                w[bi] = -INFINITY;
                sel |= 1u << bi;
            }
        }
    }

    A.x = (sel & 1u)   ? A.x : BETA;
    A.y = (sel & 2u)   ? A.y : BETA;
    A.z = (sel & 4u)   ? A.z : BETA;
    A.w = (sel & 8u)   ? A.w : BETA;
    B.x = (sel & 16u)  ? B.x : BETA;
    B.y = (sel & 32u)  ? B.y : BETA;
    B.z = (sel & 64u)  ? B.z : BETA;
    B.w = (sel & 128u) ? B.w : BETA;

    out4[lane] = A;
    out4[lane + 32] = B;
}

extern "C" void kernel_launch(void* const* d_in, const int* in_sizes, int n_in,
                              void* d_out, int out_size)
{
    const float* x = (const float*)d_in[0];
    float* out = (float*)d_out;
    int n_rows = in_sizes[0] / E;

    const int threads = 256;               // 8 warps = 8 rows per block
    int blocks = (n_rows + 7) / 8;
    keep_topk_kernel<<<blocks, threads>>>(x, out, n_rows);
}

// round 2
// speedup vs baseline: 2.0732x; 2.0732x over previous
#include <cuda_runtime.h>
#include <math.h>

#define BETA 1000000.0f
#define FULL 0xFFFFFFFFu

// compare-exchange: a <- max, b <- min  (descending order)
__device__ __forceinline__ void ce(float& a, float& b) {
    float lo = fminf(a, b);
    a = fmaxf(a, b);
    b = lo;
}

// Batcher odd-even mergesort, 8 inputs, 19 comparators, descending.
__device__ __forceinline__ void sort8_desc(float s[8]) {
    ce(s[0],s[1]); ce(s[2],s[3]); ce(s[4],s[5]); ce(s[6],s[7]);
    ce(s[0],s[2]); ce(s[1],s[3]); ce(s[4],s[6]); ce(s[5],s[7]);
    ce(s[1],s[2]); ce(s[5],s[6]);
    ce(s[0],s[4]); ce(s[1],s[5]); ce(s[2],s[6]); ce(s[3],s[7]);
    ce(s[2],s[4]); ce(s[3],s[5]);
    ce(s[1],s[2]); ce(s[3],s[4]); ce(s[5],s[6]);
}

// a, b sorted descending. a <- top-8 of (a ∪ b), sorted descending.
// max(a_i, b_{7-i}) is the top-8 multiset and is bitonic -> 3-stage bitonic merge.
__device__ __forceinline__ void merge_top8(float a[8], const float b[8]) {
    float m[8];
    #pragma unroll
    for (int i = 0; i < 8; i++) m[i] = fmaxf(a[i], b[7 - i]);
    ce(m[0],m[4]); ce(m[1],m[5]); ce(m[2],m[6]); ce(m[3],m[7]);
    ce(m[0],m[2]); ce(m[1],m[3]); ce(m[4],m[6]); ce(m[5],m[7]);
    ce(m[0],m[1]); ce(m[2],m[3]); ce(m[4],m[5]); ce(m[6],m[7]);
    #pragma unroll
    for (int i = 0; i < 8; i++) a[i] = m[i];
}

// 4 rows per warp: 8-lane group per row, 32 values per lane.
__global__ void __launch_bounds__(256, 4) keep_topk_kernel(
    const float* __restrict__ x, float* __restrict__ out, int n_rows)
{
    int lane = threadIdx.x & 31;
    int warp = (blockIdx.x * blockDim.x + threadIdx.x) >> 5;
    int g = lane >> 3;     // which of the warp's 4 rows
    int j = lane & 7;      // lane within the 8-lane row group
    int row = warp * 4 + g;
    bool valid = (row < n_rows);
    int row_c = valid ? row : (n_rows - 1);   // keep all lanes shuffle-active

    const float4* in4 = reinterpret_cast<const float4*>(x) + (size_t)row_c * 64;
    float4* out4 = reinterpret_cast<float4*>(out) + (size_t)row_c * 64;

    // lane j holds row elements 32t + 4j + c  (t=0..7, c=0..3), slot b = 4t+c
    float v[32];
    #pragma unroll
    for (int t = 0; t < 8; t++) {
        float4 q = in4[j + 8 * t];
        v[4*t+0] = q.x; v[4*t+1] = q.y; v[4*t+2] = q.z; v[4*t+3] = q.w;
    }

    // ---- local top-8 of 32 (sorted descending in s) ----
    float s[8], u[8];
    #pragma unroll
    for (int i = 0; i < 8; i++) s[i] = v[i];
    sort8_desc(s);
    #pragma unroll
    for (int i = 0; i < 8; i++) u[i] = v[8 + i];
    sort8_desc(u);
    merge_top8(s, u);
    #pragma unroll
    for (int i = 0; i < 8; i++) u[i] = v[16 + i];
    sort8_desc(u);
    merge_top8(s, u);
    #pragma unroll
    for (int i = 0; i < 8; i++) u[i] = v[24 + i];
    sort8_desc(u);
    merge_top8(s, u);

    // ---- cross-lane merge within the 8-lane group (3 butterfly stages) ----
    #pragma unroll
    for (int d = 1; d < 8; d <<= 1) {
        float p[8];
        #pragma unroll
        for (int i = 0; i < 8; i++) p[i] = __shfl_xor_sync(FULL, s[i], d);
        merge_top8(s, p);
    }

    float t8 = s[7];   // 8th largest value of the row (all group lanes agree)

    // count of values >= t8 across the group
    int n = 0;
    #pragma unroll
    for (int i = 0; i < 32; i++) n += (v[i] >= t8) ? 1 : 0;
    #pragma unroll
    for (int d = 1; d < 8; d <<= 1) n += __shfl_xor_sync(FULL, n, d);

    if (n == 8) {
        // common path: no ties straddling the boundary
        if (valid) {
            #pragma unroll
            for (int t = 0; t < 8; t++) {
                float4 o;
                o.x = (v[4*t+0] >= t8) ? v[4*t+0] : BETA;
                o.y = (v[4*t+1] >= t8) ? v[4*t+1] : BETA;
                o.z = (v[4*t+2] >= t8) ? v[4*t+2] : BETA;
                o.w = (v[4*t+3] >= t8) ? v[4*t+3] : BETA;
                out4[j + 8 * t] = o;
            }
        }
    } else {
        // rare: values equal to t8 straddle the top-8 boundary.
        // jax.lax.top_k keeps lowest global indices among ties.
        unsigned gmask = 0xFFu << (lane & 24);  // this group's lanes
        unsigned gt = 0, eq = 0;
        #pragma unroll
        for (int i = 0; i < 32; i++) {
            gt |= (v[i] >  t8 ? 1u : 0u) << i;
            eq |= (v[i] == t8 ? 1u : 0u) << i;
        }
        int ngt = __popc(gt);
        #pragma unroll
        for (int d = 1; d < 8; d <<= 1) ngt += __shfl_xor_sync(gmask, ngt, d);

        unsigned sel = gt;
        for (int k = ngt; k < 8; k++) {
            int b = __ffs(eq) - 1;  // lowest eq slot = lowest global idx in lane
            int gidx = (eq != 0u) ? ((b >> 2) * 32 + 4 * j + (b & 3)) : 0x7FFFFFFF;
            int gmin = gidx;
            #pragma unroll
            for (int d = 1; d < 8; d <<= 1)
                gmin = min(gmin, __shfl_xor_sync(gmask, gmin, d));
            if (eq != 0u && gidx == gmin) {
                sel |= 1u << b;
                eq &= ~(1u << b);
            }
        }
        if (valid) {
            #pragma unroll
            for (int t = 0; t < 8; t++) {
                float4 o;
                o.x = ((sel >> (4*t+0)) & 1u) ? v[4*t+0] : BETA;
                o.y = ((sel >> (4*t+1)) & 1u) ? v[4*t+1] : BETA;
                o.z = ((sel >> (4*t+2)) & 1u) ? v[4*t+2] : BETA;
                o.w = ((sel >> (4*t+3)) & 1u) ? v[4*t+3] : BETA;
                out4[j + 8 * t] = o;
            }
        }
    }
}

extern "C" void kernel_launch(void* const* d_in, const int* in_sizes, int n_in,
                              void* d_out, int out_size)
{
    const float* x = (const float*)d_in[0];
    float* out = (float*)d_out;
    int n_rows = in_sizes[0] / 256;

    // 256 threads = 8 warps = 32 rows per block
    int blocks = (n_rows + 31) / 32;
    keep_topk_kernel<<<blocks, 256>>>(x, out, n_rows);
}